// round 1
// baseline (speedup 1.0000x reference)
#include <cuda_runtime.h>

#define N_VERTS 53215
#define N_ROWS  (3 * N_VERTS)   // 159645
#define EXP_DIM 29
#define SHP_DIM 199

// Scratch for the intermediate vertex vector (static: allocation guards forbid cudaMalloc)
__device__ float g_verts[N_ROWS];

// ---------------------------------------------------------------------------
// Kernel 1: warp-per-row fused double GEMV
//   g_verts[r] = u[r] + dot(w_exp[r,:], a_exp) + dot(w_shp[r,:], a_shp)
// Lanes read consecutive columns -> coalesced 128B transactions.
// ---------------------------------------------------------------------------
__global__ void __launch_bounds__(256)
pca_gemv_kernel(const float* __restrict__ a_exp,
                const float* __restrict__ a_shp,
                const float* __restrict__ u,
                const float* __restrict__ w_exp,
                const float* __restrict__ w_shp)
{
    const int warp = (blockIdx.x * blockDim.x + threadIdx.x) >> 5;
    const int lane = threadIdx.x & 31;
    if (warp >= N_ROWS) return;

    const float* __restrict__ we = w_exp + (size_t)warp * EXP_DIM;
    const float* __restrict__ ws = w_shp + (size_t)warp * SHP_DIM;

    float acc = 0.0f;

    // EXP part: 29 columns, one strided pass (lanes 29..31 idle)
    if (lane < EXP_DIM)
        acc = we[lane] * __ldg(a_exp + lane);

    // SHP part: 199 columns, 7 strided passes (last partial)
    #pragma unroll
    for (int k = lane; k < SHP_DIM; k += 32)
        acc += ws[k] * __ldg(a_shp + k);

    // warp reduction
    #pragma unroll
    for (int off = 16; off > 0; off >>= 1)
        acc += __shfl_down_sync(0xffffffffu, acc, off);

    if (lane == 0)
        g_verts[warp] = acc + u[warp];
}

// ---------------------------------------------------------------------------
// Kernel 2: per-vertex affine transform + aspect scale.
// Closed form of _transform_matrix(pose, 450):
//   s  = p3 + p7 + p11
//   out_x = (s*(p0*x + p1*y + p2*z)  + p3)          * (224/450)
//   out_y = (-s*(p4*x + p5*y + p6*z) - p7 + 450)    * (224/450)
//   out_z =  s*(p8*x + p9*y + p10*z)                * 1
// ---------------------------------------------------------------------------
__global__ void __launch_bounds__(256)
pca_xform_kernel(const float* __restrict__ pose,
                 float* __restrict__ out)
{
    const int v = blockIdx.x * blockDim.x + threadIdx.x;
    if (v >= N_VERTS) return;

    const float p0 = __ldg(pose + 0),  p1 = __ldg(pose + 1),  p2  = __ldg(pose + 2),  p3  = __ldg(pose + 3);
    const float p4 = __ldg(pose + 4),  p5 = __ldg(pose + 5),  p6  = __ldg(pose + 6),  p7  = __ldg(pose + 7);
    const float p8 = __ldg(pose + 8),  p9 = __ldg(pose + 9),  p10 = __ldg(pose + 10), p11 = __ldg(pose + 11);

    const float s = p3 + p7 + p11;
    const float aspect_xy = 224.0f / 450.0f;

    const float x = g_verts[3 * v + 0];
    const float y = g_verts[3 * v + 1];
    const float z = g_verts[3 * v + 2];

    const float ox = ( s * (p0 * x + p1 * y + p2  * z) + p3)          * aspect_xy;
    const float oy = (-s * (p4 * x + p5 * y + p6  * z) - p7 + 450.0f) * aspect_xy;
    const float oz =   s * (p8 * x + p9 * y + p10 * z);

    out[3 * v + 0] = ox;
    out[3 * v + 1] = oy;
    out[3 * v + 2] = oz;
}

// ---------------------------------------------------------------------------
// Entry point
// Input order (metadata): pose_3DMM, alpha_exp, alpha_shp, u_base, w_exp_base, w_shp_base
// ---------------------------------------------------------------------------
extern "C" void kernel_launch(void* const* d_in, const int* in_sizes, int n_in,
                              void* d_out, int out_size)
{
    const float* pose  = (const float*)d_in[0];
    const float* a_exp = (const float*)d_in[1];
    const float* a_shp = (const float*)d_in[2];
    const float* u     = (const float*)d_in[3];
    const float* w_exp = (const float*)d_in[4];
    const float* w_shp = (const float*)d_in[5];
    float* out = (float*)d_out;

    // Kernel 1: one warp per row, 8 warps per 256-thread block
    const int warps_per_block = 256 / 32;
    const int blocks1 = (N_ROWS + warps_per_block - 1) / warps_per_block;
    pca_gemv_kernel<<<blocks1, 256>>>(a_exp, a_shp, u, w_exp, w_shp);

    // Kernel 2: one thread per vertex
    const int blocks2 = (N_VERTS + 255) / 256;
    pca_xform_kernel<<<blocks2, 256>>>(pose, out);
}

// round 2
// speedup vs baseline: 1.1029x; 1.1029x over previous
#include <cuda_runtime.h>

#define N_VERTS 53215
#define EXP_DIM 29
#define SHP_DIM 199
#define SHP3    (3 * SHP_DIM)   // 597
#define EXP3    (3 * EXP_DIM)   // 87

// ---------------------------------------------------------------------------
// Fused kernel: one warp per vertex.
// The 3 rows (x,y,z) of vertex v occupy a CONTIGUOUS block:
//   w_shp[3v*199 .. 3v*199+596], w_exp[3v*29 .. 3v*29+86]
// The warp streams the whole block with consecutive-lane loads (fully
// coalesced, no per-row tail waste), routing each element into one of three
// accumulators by its position. Then 3 warp reductions, closed-form
// transform, direct store to out.
//
// Transform (derived from _transform_matrix(pose, 450)):
//   s  = p3 + p7 + p11
//   ox = ( s*(p0x + p1y + p2z)  + p3)        * (224/450)
//   oy = (-s*(p4x + p5y + p6z)  - p7 + 450)  * (224/450)
//   oz =   s*(p8x + p9y + p10z)
// ---------------------------------------------------------------------------
__global__ void __launch_bounds__(256)
pca_fused_kernel(const float* __restrict__ pose,
                 const float* __restrict__ a_exp,
                 const float* __restrict__ a_shp,
                 const float* __restrict__ u,
                 const float* __restrict__ w_exp,
                 const float* __restrict__ w_shp,
                 float* __restrict__ out)
{
    const int warp = (blockIdx.x * blockDim.x + threadIdx.x) >> 5;
    const int lane = threadIdx.x & 31;
    if (warp >= N_VERTS) return;

    const float* __restrict__ ws = w_shp + (size_t)warp * SHP3;
    const float* __restrict__ we = w_exp + (size_t)warp * EXP3;

    float acc0 = 0.0f, acc1 = 0.0f, acc2 = 0.0f;

    // ---- SHP block: 597 contiguous floats, 19 strided passes ----
    #pragma unroll
    for (int i = 0; i < 19; i++) {
        const int j = i * 32 + lane;
        if (j < SHP3) {
            const float w = ws[j];
            // column index = j mod 199, row = j / 199 (only 3 segments)
            int col; int row;
            if (j < SHP_DIM)            { col = j;               row = 0; }
            else if (j < 2 * SHP_DIM)   { col = j - SHP_DIM;     row = 1; }
            else                        { col = j - 2 * SHP_DIM; row = 2; }
            const float p = w * __ldg(a_shp + col);
            if (row == 0) acc0 += p;
            else if (row == 1) acc1 += p;
            else acc2 += p;
        }
    }

    // ---- EXP block: 87 contiguous floats, 3 strided passes ----
    #pragma unroll
    for (int i = 0; i < 3; i++) {
        const int j = i * 32 + lane;
        if (j < EXP3) {
            const float w = we[j];
            int col; int row;
            if (j < EXP_DIM)            { col = j;               row = 0; }
            else if (j < 2 * EXP_DIM)   { col = j - EXP_DIM;     row = 1; }
            else                        { col = j - 2 * EXP_DIM; row = 2; }
            const float p = w * __ldg(a_exp + col);
            if (row == 0) acc0 += p;
            else if (row == 1) acc1 += p;
            else acc2 += p;
        }
    }

    // ---- warp reductions (3 values) ----
    #pragma unroll
    for (int off = 16; off > 0; off >>= 1) {
        acc0 += __shfl_down_sync(0xffffffffu, acc0, off);
        acc1 += __shfl_down_sync(0xffffffffu, acc1, off);
        acc2 += __shfl_down_sync(0xffffffffu, acc2, off);
    }

    if (lane == 0) {
        const float x = acc0 + __ldg(u + 3 * warp + 0);
        const float y = acc1 + __ldg(u + 3 * warp + 1);
        const float z = acc2 + __ldg(u + 3 * warp + 2);

        const float p0 = __ldg(pose + 0),  p1 = __ldg(pose + 1),  p2  = __ldg(pose + 2),  p3  = __ldg(pose + 3);
        const float p4 = __ldg(pose + 4),  p5 = __ldg(pose + 5),  p6  = __ldg(pose + 6),  p7  = __ldg(pose + 7);
        const float p8 = __ldg(pose + 8),  p9 = __ldg(pose + 9),  p10 = __ldg(pose + 10), p11 = __ldg(pose + 11);

        const float s = p3 + p7 + p11;
        const float aspect_xy = 224.0f / 450.0f;

        out[3 * warp + 0] = ( s * (p0 * x + p1 * y + p2  * z) + p3)          * aspect_xy;
        out[3 * warp + 1] = (-s * (p4 * x + p5 * y + p6  * z) - p7 + 450.0f) * aspect_xy;
        out[3 * warp + 2] =   s * (p8 * x + p9 * y + p10 * z);
    }
}

// ---------------------------------------------------------------------------
// Entry point
// Input order: pose_3DMM, alpha_exp, alpha_shp, u_base, w_exp_base, w_shp_base
// ---------------------------------------------------------------------------
extern "C" void kernel_launch(void* const* d_in, const int* in_sizes, int n_in,
                              void* d_out, int out_size)
{
    const float* pose  = (const float*)d_in[0];
    const float* a_exp = (const float*)d_in[1];
    const float* a_shp = (const float*)d_in[2];
    const float* u     = (const float*)d_in[3];
    const float* w_exp = (const float*)d_in[4];
    const float* w_shp = (const float*)d_in[5];
    float* out = (float*)d_out;

    const int warps_per_block = 256 / 32;
    const int blocks = (N_VERTS + warps_per_block - 1) / warps_per_block;
    pca_fused_kernel<<<blocks, 256>>>(pose, a_exp, a_shp, u, w_exp, w_shp, out);
}